// round 5
// baseline (speedup 1.0000x reference)
#include <cuda_runtime.h>
#include <cstdint>

// ---------------- problem constants ----------------
#define B_     4096
#define OBS_   64
#define EP_    10
#define IN_    640      // OBS*EP
#define H_     1024
#define AD_    16
#define DP_    10
#define OUT_   160      // AD*DP
#define T_     8

#define CDECAY 0.5f
#define VTH    0.5f
#define THV   (-0.172f)
#define THU    0.529f
#define THR    0.021f
#define THS    0.132f

static const size_t NBH = (size_t)B_ * H_;
static const size_t NBO = (size_t)B_ * OUT_;
static const size_t NBI = (size_t)B_ * IN_;

// fp32 state layout inside g_state
#define OFF_CUR1 ((size_t)0)
#define OFF_V1   ((size_t)1 * NBH)
#define OFF_R1   ((size_t)2 * NBH)
#define OFF_CUR2 ((size_t)3 * NBH)
#define OFF_V2   ((size_t)4 * NBH)
#define OFF_R2   ((size_t)5 * NBH)
#define OFF_O    ((size_t)6 * NBH)
#define OFF_CURO (OFF_O + (size_t)0 * NBO)
#define OFF_VO   (OFF_O + (size_t)1 * NBO)
#define OFF_RO   (OFF_O + (size_t)2 * NBO)
#define OFF_SO0  (OFF_O + (size_t)3 * NBO)
#define OFF_SO1  (OFF_O + (size_t)4 * NBO)
#define OFF_ACC  (OFF_O + (size_t)5 * NBO)
#define STATE_TOTAL ((size_t)6 * NBH + (size_t)6 * NBO)

// ---------------- device scratch ----------------
__device__ __align__(128) int8_t g_spikes[(size_t)T_ * (size_t)B_ * (size_t)IN_]; // 21 MB
__device__ __align__(128) int8_t g_s1[(size_t)B_ * (size_t)H_];
__device__ __align__(128) int8_t g_s2[(size_t)B_ * (size_t)H_];
__device__ __align__(128) float g_x3[(size_t)B_ * (size_t)OUT_];
__device__ __align__(128) float g_state[(size_t)6 * (size_t)B_ * (size_t)H_ + (size_t)6 * (size_t)B_ * (size_t)OUT_];

// ---------------- helpers ----------------
__device__ __forceinline__ uint32_t smem_u32(const void* p) {
    uint32_t a;
    asm("{ .reg .u64 t; cvta.to.shared.u64 t, %1; cvt.u32.u64 %0, t; }" : "=r"(a) : "l"(p));
    return a;
}
__device__ __forceinline__ unsigned long long lds64(uint32_t addr) {
    unsigned long long u;
    asm volatile("ld.shared.b64 %0, [%1];" : "=l"(u) : "r"(addr));
    return u;
}
// packed fp32 pair FMA: per-lane IEEE RN fp32 fma (bitwise == scalar FFMA chain)
__device__ __forceinline__ void fma2(unsigned long long& d, unsigned long long a, unsigned long long b) {
    asm("fma.rn.f32x2 %0, %1, %2, %0;" : "+l"(d) : "l"(a), "l"(b));
}
__device__ __forceinline__ float f2lo(unsigned long long u) {
    return __int_as_float((int)(unsigned)(u & 0xffffffffull));
}
__device__ __forceinline__ float f2hi(unsigned long long u) {
    return __int_as_float((int)(unsigned)(u >> 32));
}

// ---------------- f32x2 SGEMM, sequential-k fp32 semantics ----------------
// C[m][n] = sum_{k=0..K-1, in order} A[m][k]*W[n][k]  (fp32 RN FMA chain per output)
// A: s8 spikes [M][KBASE] (values 0/1, exact). W: fp32 [N][KBASE] row-major.
// CTA 128x128, BK=16, 256 threads, per-thread 8x8 outputs as 8x4 f32x2.
// Dynamic smem: Asd [2][16][128] float2 (dup pairs) | Wsm [2][16][132] float
template<int KBASE, bool FUSE>
__global__ __launch_bounds__(256) void sgemm_f32x2(
    const int8_t* __restrict__ A, const float* __restrict__ W,
    const float* __restrict__ bias, float* __restrict__ Cout,
    float* __restrict__ cur, float* __restrict__ v, float* __restrict__ r,
    int8_t* __restrict__ sio, int Ntot) {

    constexpr int KT = KBASE / 16;
    constexpr int LDW = 132;

    extern __shared__ float sm[];
    float2* Asd = (float2*)sm;                 // [2][16][128] float2, 16384 B per buf
    float*  Wsm = sm + 2 * 16 * 256;           // [2][16][132], 8448 B per buf
    const uint32_t asb = smem_u32(sm);

    const int tid  = threadIdx.x;
    const int trow = tid >> 4;    // 0..15
    const int tcol = tid & 15;    // 0..15
    const int bm0 = blockIdx.y * 128;
    const int bn0 = blockIdx.x * 128;

    const bool aown = tid < 128;
    const int  wn  = tid >> 1;
    const int  wkh = tid & 1;
    const int  gn  = bn0 + wn;
    const bool wok = gn < Ntot;
    const float* wrow = W + (size_t)(wok ? gn : 0) * KBASE + wkh * 8;

    uint4  areg;
    float4 w0r, w1r;

    auto ldg = [&](int i) {
        if (aown) areg = *(const uint4*)(A + (size_t)(bm0 + tid) * KBASE + i * 16);
        if (wok) {
            w0r = *(const float4*)(wrow + i * 16);
            w1r = *(const float4*)(wrow + i * 16 + 4);
        } else {
            w0r = make_float4(0.f, 0.f, 0.f, 0.f);
            w1r = w0r;
        }
    };
    auto sts = [&](int buf) {
        if (aown) {
#pragma unroll
            for (int q = 0; q < 4; q++) {
                uint32_t u = ((const uint32_t*)&areg)[q];
#pragma unroll
                for (int b = 0; b < 4; b++) {
                    float a = (float)(int)(signed char)((u >> (8 * b)) & 0xff);
                    Asd[(buf * 16 + q * 4 + b) * 128 + tid] = make_float2(a, a);
                }
            }
        }
#pragma unroll
        for (int j = 0; j < 4; j++) {
            Wsm[(buf * 16 + wkh * 8 + j) * LDW + wn]     = (&w0r.x)[j];
            Wsm[(buf * 16 + wkh * 8 + 4 + j) * LDW + wn] = (&w1r.x)[j];
        }
    };

    unsigned long long acc[8][4];
#pragma unroll
    for (int i = 0; i < 8; i++)
#pragma unroll
        for (int j = 0; j < 4; j++) acc[i][j] = 0ull;

    ldg(0); sts(0);
    __syncthreads();

    for (int i = 0; i < KT; i++) {
        const int buf = i & 1;
        if (i + 1 < KT) ldg(i + 1);

        const uint32_t abase = asb + (uint32_t)buf * 16384u + (uint32_t)(trow * 8) * 8u;
        const uint32_t wbase = asb + 32768u + (uint32_t)buf * 8448u + (uint32_t)(tcol * 8) * 4u;
#pragma unroll
        for (int k = 0; k < 16; k++) {
            const uint32_t ak = abase + (uint32_t)k * 1024u;
            const uint32_t wk = wbase + (uint32_t)k * (LDW * 4);
            unsigned long long aa[8], ww[4];
#pragma unroll
            for (int ii = 0; ii < 8; ii++) aa[ii] = lds64(ak + ii * 8);
#pragma unroll
            for (int jj = 0; jj < 4; jj++) ww[jj] = lds64(wk + jj * 8);
#pragma unroll
            for (int ii = 0; ii < 8; ii++)
#pragma unroll
                for (int jj = 0; jj < 4; jj++) fma2(acc[ii][jj], aa[ii], ww[jj]);
        }
        if (i + 1 < KT) sts((i + 1) & 1);
        __syncthreads();
    }

    if (FUSE) {
        float bj[8];
#pragma unroll
        for (int cc = 0; cc < 8; cc++) bj[cc] = bias[bn0 + tcol * 8 + cc];
#pragma unroll
        for (int i = 0; i < 8; i++) {
            size_t base = (size_t)(bm0 + trow * 8 + i) * Ntot + bn0 + tcol * 8;
#pragma unroll
            for (int j = 0; j < 4; j++) {
#pragma unroll
                for (int e = 0; e < 2; e++) {
                    int cc = 2 * j + e;
                    size_t idx = base + cc;
                    float xv = e ? f2hi(acc[i][j]) : f2lo(acc[i][j]);
                    float c  = cur[idx] * CDECAY + xv + bj[cc];
                    float vv = v[idx], rr = r[idx];
                    float ss = (float)sio[idx];
                    vv = vv * (1.0f - ss) + ss * THR;
                    rr = rr + ss * THS;
                    float vd = vv * vv - vv - rr + c;
                    float rd = THV * vv - THU * rr;
                    vv += vd; rr += rd;
                    float sn = vv > VTH ? 1.0f : 0.0f;
                    cur[idx] = c; v[idx] = vv; r[idx] = rr;
                    sio[idx] = (int8_t)sn;
                }
            }
        }
    } else {
#pragma unroll
        for (int i = 0; i < 8; i++) {
            int row = bm0 + trow * 8 + i;
#pragma unroll
            for (int j = 0; j < 4; j++) {
                int col = bn0 + tcol * 8 + 2 * j;
                if (col + 1 < Ntot) {
                    *(float2*)&Cout[(size_t)row * Ntot + col] =
                        make_float2(f2lo(acc[i][j]), f2hi(acc[i][j]));
                } else if (col < Ntot) {
                    Cout[(size_t)row * Ntot + col] = f2lo(acc[i][j]);
                }
            }
        }
    }
}

// ---------------- elementwise kernels (R1 semantics) ----------------
__global__ void zero_kernel() {
    size_t i = (size_t)blockIdx.x * blockDim.x + threadIdx.x;
    size_t stride = (size_t)gridDim.x * blockDim.x;
    for (size_t j = i; j < STATE_TOTAL; j += stride) g_state[j] = 0.0f;
    uint32_t* s1 = (uint32_t*)g_s1;
    uint32_t* s2 = (uint32_t*)g_s2;
    for (size_t j = i; j < NBH / 4; j += stride) { s1[j] = 0u; s2[j] = 0u; }
}

__global__ void encoder_kernel(const float* __restrict__ obs,
                               const float* __restrict__ mean,
                               const float* __restrict__ stdv) {
    int idx = blockIdx.x * blockDim.x + threadIdx.x;
    if (idx >= B_ * IN_) return;
    int b = idx / IN_;
    int i = idx - b * IN_;
    int o = i / EP_;
    float d  = obs[b * OBS_ + o] - mean[i];
    float sd = stdv[i];
    float a  = expf(-0.5f * d * d / (sd * sd));
    float volt = 0.0f;
#pragma unroll
    for (int t = 0; t < T_; t++) {
        volt += a;
        float s = volt > 1.0f ? 1.0f : 0.0f;
        volt -= s;
        g_spikes[(size_t)t * NBI + idx] = (int8_t)s;
    }
}

__global__ void neuron_out_kernel(const float* __restrict__ x, const float* __restrict__ bias,
                                  const float* __restrict__ conn_w, const float* __restrict__ conn_b,
                                  const float* __restrict__ s_prev, float* __restrict__ s_new,
                                  float* __restrict__ cur, float* __restrict__ v,
                                  float* __restrict__ r, float* __restrict__ acc) {
    int idx = blockIdx.x * blockDim.x + threadIdx.x;
    if (idx >= B_ * OUT_) return;
    int b  = idx / OUT_;
    int jg = idx - b * OUT_;
    int a  = jg / DP_;
    int j  = jg - a * DP_;
    float lat = conn_b[jg];
    const float* sp = s_prev + (size_t)b * OUT_ + a * DP_;
    const float* cw = conn_w + (size_t)(a * DP_ + j) * DP_;
#pragma unroll
    for (int k = 0; k < DP_; k++) lat += sp[k] * cw[k];

    float c  = cur[idx] * CDECAY + x[idx] + bias[jg] + lat;
    float vv = v[idx], rr = r[idx], ss = s_prev[idx];
    vv = vv * (1.0f - ss) + ss * THR;
    rr = rr + ss * THS;
    float vd = vv * vv - vv - rr + c;
    float rd = THV * vv - THU * rr;
    vv += vd; rr += rd;
    ss = vv > VTH ? 1.0f : 0.0f;
    cur[idx] = c; v[idx] = vv; r[idx] = rr;
    s_new[idx] = ss;
    acc[idx] += ss;
}

__global__ void decode_kernel(const float* __restrict__ acc, const float* __restrict__ dec_w,
                              const float* __restrict__ dec_b, float* __restrict__ out) {
    int idx = blockIdx.x * blockDim.x + threadIdx.x;
    if (idx >= B_ * AD_) return;
    int b = idx / AD_;
    int a = idx - b * AD_;
    float raw = dec_b[a];
    const float* ap = acc + (size_t)b * OUT_ + a * DP_;
    const float* wp = dec_w + a * DP_;
#pragma unroll
    for (int p = 0; p < DP_; p++) raw += (ap[p] * 0.125f) * wp[p];
    out[idx] = tanhf(raw);
}

// ---------------- launch ----------------
extern "C" void kernel_launch(void* const* d_in, const int* in_sizes, int n_in,
                              void* d_out, int out_size) {
    const float* obs    = (const float*)d_in[0];
    const float* mean   = (const float*)d_in[1];
    const float* stdv   = (const float*)d_in[2];
    const float* w1     = (const float*)d_in[3];
    const float* b1     = (const float*)d_in[4];
    const float* w2     = (const float*)d_in[5];
    const float* b2     = (const float*)d_in[6];
    const float* w_out  = (const float*)d_in[7];
    const float* b_out  = (const float*)d_in[8];
    const float* conn_w = (const float*)d_in[9];
    const float* conn_b = (const float*)d_in[10];
    const float* dec_w  = (const float*)d_in[11];
    const float* dec_b  = (const float*)d_in[12];
    float* out = (float*)d_out;

    int8_t *spikes, *s1, *s2;
    float *x3, *st;
    cudaGetSymbolAddress((void**)&spikes, g_spikes);
    cudaGetSymbolAddress((void**)&s1, g_s1);
    cudaGetSymbolAddress((void**)&s2, g_s2);
    cudaGetSymbolAddress((void**)&x3, g_x3);
    cudaGetSymbolAddress((void**)&st, g_state);

    const int smem_bytes = 2 * 16 * 256 * 4 + 2 * 16 * 132 * 4;  // 49664
    cudaFuncSetAttribute(sgemm_f32x2<640, true>,   cudaFuncAttributeMaxDynamicSharedMemorySize, smem_bytes);
    cudaFuncSetAttribute(sgemm_f32x2<1024, true>,  cudaFuncAttributeMaxDynamicSharedMemorySize, smem_bytes);
    cudaFuncSetAttribute(sgemm_f32x2<1024, false>, cudaFuncAttributeMaxDynamicSharedMemorySize, smem_bytes);

    zero_kernel<<<1024, 256>>>();
    encoder_kernel<<<(B_ * IN_ + 255) / 256, 256>>>(obs, mean, stdv);

    dim3 gH(H_ / 128, B_ / 128);   // (8, 32)
    dim3 gO(2, B_ / 128);          // (2, 32): 256 cols >= 160
    int nboBlocks = (int)((NBO + 255) / 256);

    for (int t = 0; t < T_; t++) {
        sgemm_f32x2<640, true><<<gH, 256, smem_bytes>>>(
            spikes + (size_t)t * NBI, w1, b1, nullptr,
            st + OFF_CUR1, st + OFF_V1, st + OFF_R1, s1, H_);

        sgemm_f32x2<1024, true><<<gH, 256, smem_bytes>>>(
            s1, w2, b2, nullptr,
            st + OFF_CUR2, st + OFF_V2, st + OFF_R2, s2, H_);

        sgemm_f32x2<1024, false><<<gO, 256, smem_bytes>>>(
            s2, w_out, nullptr, x3, nullptr, nullptr, nullptr, nullptr, OUT_);

        float* sp = st + ((t & 1) == 0 ? OFF_SO0 : OFF_SO1);
        float* sn = st + ((t & 1) == 0 ? OFF_SO1 : OFF_SO0);
        neuron_out_kernel<<<nboBlocks, 256>>>(x3, b_out, conn_w, conn_b, sp, sn,
            st + OFF_CURO, st + OFF_VO, st + OFF_RO, st + OFF_ACC);
    }

    decode_kernel<<<(B_ * AD_ + 255) / 256, 256>>>(st + OFF_ACC, dec_w, dec_b, out);
}

// round 6
// speedup vs baseline: 1.1215x; 1.1215x over previous
#include <cuda_runtime.h>
#include <cstdint>

// ---------------- problem constants ----------------
#define B_     4096
#define OBS_   64
#define EP_    10
#define IN_    640      // OBS*EP
#define H_     1024
#define AD_    16
#define DP_    10
#define OUT_   160      // AD*DP
#define T_     8

#define CDECAY 0.5f
#define VTH    0.5f
#define THV   (-0.172f)
#define THU    0.529f
#define THR    0.021f
#define THS    0.132f

static const size_t NBH = (size_t)B_ * H_;
static const size_t NBO = (size_t)B_ * OUT_;
static const size_t NBI = (size_t)B_ * IN_;

// fp32 state layout inside g_state
#define OFF_CUR1 ((size_t)0)
#define OFF_V1   ((size_t)1 * NBH)
#define OFF_R1   ((size_t)2 * NBH)
#define OFF_CUR2 ((size_t)3 * NBH)
#define OFF_V2   ((size_t)4 * NBH)
#define OFF_R2   ((size_t)5 * NBH)
#define OFF_O    ((size_t)6 * NBH)
#define OFF_CURO (OFF_O + (size_t)0 * NBO)
#define OFF_VO   (OFF_O + (size_t)1 * NBO)
#define OFF_RO   (OFF_O + (size_t)2 * NBO)
#define OFF_SO0  (OFF_O + (size_t)3 * NBO)
#define OFF_SO1  (OFF_O + (size_t)4 * NBO)
#define OFF_ACC  (OFF_O + (size_t)5 * NBO)
#define STATE_TOTAL ((size_t)6 * NBH + (size_t)6 * NBO)

// ---------------- device scratch ----------------
__device__ __align__(128) int8_t g_spikes[(size_t)T_ * (size_t)B_ * (size_t)IN_]; // 21 MB
__device__ __align__(128) int8_t g_s1[(size_t)B_ * (size_t)H_];
__device__ __align__(128) int8_t g_s2[(size_t)B_ * (size_t)H_];
__device__ __align__(128) float g_x3[(size_t)B_ * (size_t)OUT_];
__device__ __align__(128) float g_state[(size_t)6 * (size_t)B_ * (size_t)H_ + (size_t)6 * (size_t)B_ * (size_t)OUT_];

// ---------------- helpers ----------------
__device__ __forceinline__ uint32_t smem_u32(const void* p) {
    uint32_t a;
    asm("{ .reg .u64 t; cvta.to.shared.u64 t, %1; cvt.u32.u64 %0, t; }" : "=r"(a) : "l"(p));
    return a;
}
__device__ __forceinline__ void lds_v2u64(unsigned long long& a, unsigned long long& b, uint32_t addr) {
    asm volatile("ld.shared.v2.u64 {%0,%1}, [%2];" : "=l"(a), "=l"(b) : "r"(addr));
}
__device__ __forceinline__ void lds_f4(float4& v, uint32_t addr) {
    asm volatile("ld.shared.v4.f32 {%0,%1,%2,%3}, [%4];"
        : "=f"(v.x), "=f"(v.y), "=f"(v.z), "=f"(v.w) : "r"(addr));
}
__device__ __forceinline__ unsigned long long dup2(float x) {
    unsigned long long d;
    uint32_t u = __float_as_uint(x);
    asm("mov.b64 %0, {%1,%1};" : "=l"(d) : "r"(u));
    return d;
}
// packed fp32 pair FMA: per-lane IEEE RN fp32 fma (bitwise == scalar FFMA chain)
__device__ __forceinline__ void fma2(unsigned long long& d, unsigned long long a, unsigned long long b) {
    asm("fma.rn.f32x2 %0, %1, %2, %0;" : "+l"(d) : "l"(a), "l"(b));
}
__device__ __forceinline__ float f2lo(unsigned long long u) {
    return __int_as_float((int)(unsigned)(u & 0xffffffffull));
}
__device__ __forceinline__ float f2hi(unsigned long long u) {
    return __int_as_float((int)(unsigned)(u >> 32));
}

// ---------------- f32x2 SGEMM, sequential-k fp32 semantics ----------------
// C[m][n] = sum_{k ascending} A[m][k]*W[n][k], fp32 RN FMA chain per output.
// A: s8 spikes [M][KBASE] (0/1). W: fp32 [N][KBASE] row-major.
// CTA tile (TM*16) x 128, 256 threads, per-thread TM rows x 8 cols (4 f32x2).
// Smem: A plain f32 k-major [2][16][BM]; W [2][16][132] f32. (a,a) packed in regs.
template<int KBASE, int TM, bool FUSE>
__global__ __launch_bounds__(256, 2) void sgemm_f32x2(
    const int8_t* __restrict__ A, const float* __restrict__ W,
    const float* __restrict__ bias, float* __restrict__ Cout,
    float* __restrict__ cur, float* __restrict__ v, float* __restrict__ r,
    int8_t* __restrict__ sio, int Ntot) {

    constexpr int BM  = TM * 16;
    constexpr int KT  = KBASE / 16;
    constexpr int LDW = 132;
    constexpr int ASZ = 16 * BM;    // floats per A buffer
    constexpr int WSZ = 16 * LDW;   // floats per W buffer

    extern __shared__ float sm[];
    const uint32_t asb = smem_u32(sm);
    const uint32_t wb0 = asb + 2 * ASZ * 4;

    const int tid  = threadIdx.x;
    const int trow = tid >> 4;    // 0..15
    const int tcol = tid & 15;    // 0..15
    const int bm0 = blockIdx.y * BM;
    const int bn0 = blockIdx.x * 128;

    const bool aown = tid < BM;
    const int  wn  = tid >> 1;
    const int  wkh = tid & 1;
    const int  gn  = bn0 + wn;
    const bool wok = gn < Ntot;
    const float* wrow = W + (size_t)(wok ? gn : 0) * KBASE + wkh * 8;

    uint4  areg;
    float4 w0r, w1r;

    auto ldg = [&](int i) {
        if (aown) areg = *(const uint4*)(A + (size_t)(bm0 + tid) * KBASE + i * 16);
        if (wok) {
            w0r = *(const float4*)(wrow + i * 16);
            w1r = *(const float4*)(wrow + i * 16 + 4);
        } else {
            w0r = make_float4(0.f, 0.f, 0.f, 0.f);
            w1r = w0r;
        }
    };
    auto sts = [&](int buf) {
        if (aown) {
            uint32_t* ai = (uint32_t*)sm + buf * ASZ + tid;
#pragma unroll
            for (int q = 0; q < 4; q++) {
                uint32_t u = ((const uint32_t*)&areg)[q];
#pragma unroll
                for (int b = 0; b < 4; b++)
                    ai[(q * 4 + b) * BM] = ((u >> (8 * b)) & 1u) * 0x3f800000u;
            }
        }
        float* wp = sm + 2 * ASZ + buf * WSZ + (wkh * 8) * LDW + wn;
#pragma unroll
        for (int j = 0; j < 4; j++) {
            wp[j * LDW]       = (&w0r.x)[j];
            wp[(4 + j) * LDW] = (&w1r.x)[j];
        }
    };

    unsigned long long acc[TM][4];
#pragma unroll
    for (int i = 0; i < TM; i++)
#pragma unroll
        for (int j = 0; j < 4; j++) acc[i][j] = 0ull;

    ldg(0); sts(0);
    __syncthreads();

    for (int i = 0; i < KT; i++) {
        const int buf = i & 1;
        if (i + 1 < KT) ldg(i + 1);

        const uint32_t abase = asb + (uint32_t)(buf * ASZ + trow * TM) * 4u;
        const uint32_t wbase = wb0 + (uint32_t)(buf * WSZ + tcol * 8) * 4u;
#pragma unroll
        for (int k = 0; k < 16; k++) {
            float4 av[TM / 4];
#pragma unroll
            for (int q = 0; q < TM / 4; q++)
                lds_f4(av[q], abase + (uint32_t)(k * BM) * 4u + q * 16u);
            unsigned long long ww[4];
            const uint32_t wk = wbase + (uint32_t)(k * LDW) * 4u;
            lds_v2u64(ww[0], ww[1], wk);
            lds_v2u64(ww[2], ww[3], wk + 16u);
            unsigned long long aa[TM];
#pragma unroll
            for (int ii = 0; ii < TM; ii++) aa[ii] = dup2(((const float*)av)[ii]);
#pragma unroll
            for (int ii = 0; ii < TM; ii++)
#pragma unroll
                for (int jj = 0; jj < 4; jj++) fma2(acc[ii][jj], aa[ii], ww[jj]);
        }
        if (i + 1 < KT) sts((i + 1) & 1);
        __syncthreads();
    }

    if (FUSE) {
        float bj[8];
#pragma unroll
        for (int cc = 0; cc < 8; cc++) bj[cc] = bias[bn0 + tcol * 8 + cc];
#pragma unroll
        for (int i = 0; i < TM; i++) {
            size_t base = (size_t)(bm0 + trow * TM + i) * Ntot + bn0 + tcol * 8;
#pragma unroll
            for (int j = 0; j < 4; j++) {
#pragma unroll
                for (int e = 0; e < 2; e++) {
                    int cc = 2 * j + e;
                    size_t idx = base + cc;
                    float xv = e ? f2hi(acc[i][j]) : f2lo(acc[i][j]);
                    float c  = cur[idx] * CDECAY + xv + bj[cc];
                    float vv = v[idx], rr = r[idx];
                    float ss = (float)sio[idx];
                    vv = vv * (1.0f - ss) + ss * THR;
                    rr = rr + ss * THS;
                    float vd = vv * vv - vv - rr + c;
                    float rd = THV * vv - THU * rr;
                    vv += vd; rr += rd;
                    float sn = vv > VTH ? 1.0f : 0.0f;
                    cur[idx] = c; v[idx] = vv; r[idx] = rr;
                    sio[idx] = (int8_t)sn;
                }
            }
        }
    } else {
#pragma unroll
        for (int i = 0; i < TM; i++) {
            int row = bm0 + trow * TM + i;
#pragma unroll
            for (int j = 0; j < 4; j++) {
                int col = bn0 + tcol * 8 + 2 * j;
                if (col + 1 < Ntot) {
                    *(float2*)&Cout[(size_t)row * Ntot + col] =
                        make_float2(f2lo(acc[i][j]), f2hi(acc[i][j]));
                } else if (col < Ntot) {
                    Cout[(size_t)row * Ntot + col] = f2lo(acc[i][j]);
                }
            }
        }
    }
}

// ---------------- elementwise kernels (R1 semantics) ----------------
__global__ void zero_kernel() {
    size_t i = (size_t)blockIdx.x * blockDim.x + threadIdx.x;
    size_t stride = (size_t)gridDim.x * blockDim.x;
    for (size_t j = i; j < STATE_TOTAL; j += stride) g_state[j] = 0.0f;
    uint32_t* s1 = (uint32_t*)g_s1;
    uint32_t* s2 = (uint32_t*)g_s2;
    for (size_t j = i; j < NBH / 4; j += stride) { s1[j] = 0u; s2[j] = 0u; }
}

__global__ void encoder_kernel(const float* __restrict__ obs,
                               const float* __restrict__ mean,
                               const float* __restrict__ stdv) {
    int idx = blockIdx.x * blockDim.x + threadIdx.x;
    if (idx >= B_ * IN_) return;
    int b = idx / IN_;
    int i = idx - b * IN_;
    int o = i / EP_;
    float d  = obs[b * OBS_ + o] - mean[i];
    float sd = stdv[i];
    float a  = expf(-0.5f * d * d / (sd * sd));
    float volt = 0.0f;
#pragma unroll
    for (int t = 0; t < T_; t++) {
        volt += a;
        float s = volt > 1.0f ? 1.0f : 0.0f;
        volt -= s;
        g_spikes[(size_t)t * NBI + idx] = (int8_t)s;
    }
}

__global__ void neuron_out_kernel(const float* __restrict__ x, const float* __restrict__ bias,
                                  const float* __restrict__ conn_w, const float* __restrict__ conn_b,
                                  const float* __restrict__ s_prev, float* __restrict__ s_new,
                                  float* __restrict__ cur, float* __restrict__ v,
                                  float* __restrict__ r, float* __restrict__ acc) {
    int idx = blockIdx.x * blockDim.x + threadIdx.x;
    if (idx >= B_ * OUT_) return;
    int b  = idx / OUT_;
    int jg = idx - b * OUT_;
    int a  = jg / DP_;
    int j  = jg - a * DP_;
    float lat = conn_b[jg];
    const float* sp = s_prev + (size_t)b * OUT_ + a * DP_;
    const float* cw = conn_w + (size_t)(a * DP_ + j) * DP_;
#pragma unroll
    for (int k = 0; k < DP_; k++) lat += sp[k] * cw[k];

    float c  = cur[idx] * CDECAY + x[idx] + bias[jg] + lat;
    float vv = v[idx], rr = r[idx], ss = s_prev[idx];
    vv = vv * (1.0f - ss) + ss * THR;
    rr = rr + ss * THS;
    float vd = vv * vv - vv - rr + c;
    float rd = THV * vv - THU * rr;
    vv += vd; rr += rd;
    ss = vv > VTH ? 1.0f : 0.0f;
    cur[idx] = c; v[idx] = vv; r[idx] = rr;
    s_new[idx] = ss;
    acc[idx] += ss;
}

__global__ void decode_kernel(const float* __restrict__ acc, const float* __restrict__ dec_w,
                              const float* __restrict__ dec_b, float* __restrict__ out) {
    int idx = blockIdx.x * blockDim.x + threadIdx.x;
    if (idx >= B_ * AD_) return;
    int b = idx / AD_;
    int a = idx - b * AD_;
    float raw = dec_b[a];
    const float* ap = acc + (size_t)b * OUT_ + a * DP_;
    const float* wp = dec_w + a * DP_;
#pragma unroll
    for (int p = 0; p < DP_; p++) raw += (ap[p] * 0.125f) * wp[p];
    out[idx] = tanhf(raw);
}

// ---------------- launch ----------------
extern "C" void kernel_launch(void* const* d_in, const int* in_sizes, int n_in,
                              void* d_out, int out_size) {
    const float* obs    = (const float*)d_in[0];
    const float* mean   = (const float*)d_in[1];
    const float* stdv   = (const float*)d_in[2];
    const float* w1     = (const float*)d_in[3];
    const float* b1     = (const float*)d_in[4];
    const float* w2     = (const float*)d_in[5];
    const float* b2     = (const float*)d_in[6];
    const float* w_out  = (const float*)d_in[7];
    const float* b_out  = (const float*)d_in[8];
    const float* conn_w = (const float*)d_in[9];
    const float* conn_b = (const float*)d_in[10];
    const float* dec_w  = (const float*)d_in[11];
    const float* dec_b  = (const float*)d_in[12];
    float* out = (float*)d_out;

    int8_t *spikes, *s1, *s2;
    float *x3, *st;
    cudaGetSymbolAddress((void**)&spikes, g_spikes);
    cudaGetSymbolAddress((void**)&s1, g_s1);
    cudaGetSymbolAddress((void**)&s2, g_s2);
    cudaGetSymbolAddress((void**)&x3, g_x3);
    cudaGetSymbolAddress((void**)&st, g_state);

    const int smemH = (2 * 16 * 128 + 2 * 16 * 132) * 4;  // 33280 B (TM=8)
    const int smemO = (2 * 16 * 64  + 2 * 16 * 132) * 4;  // 25088 B (TM=4)
    cudaFuncSetAttribute(sgemm_f32x2<640, 8, true>,   cudaFuncAttributeMaxDynamicSharedMemorySize, smemH);
    cudaFuncSetAttribute(sgemm_f32x2<1024, 8, true>,  cudaFuncAttributeMaxDynamicSharedMemorySize, smemH);
    cudaFuncSetAttribute(sgemm_f32x2<1024, 4, false>, cudaFuncAttributeMaxDynamicSharedMemorySize, smemO);

    zero_kernel<<<1024, 256>>>();
    encoder_kernel<<<(B_ * IN_ + 255) / 256, 256>>>(obs, mean, stdv);

    dim3 gH(8, 32);    // 128x128 tiles over 4096x1024
    dim3 gO(2, 64);    // 64x128 tiles over 4096x256 (>=160 cols, guarded)
    int nboBlocks = (int)((NBO + 255) / 256);

    for (int t = 0; t < T_; t++) {
        sgemm_f32x2<640, 8, true><<<gH, 256, smemH>>>(
            spikes + (size_t)t * NBI, w1, b1, nullptr,
            st + OFF_CUR1, st + OFF_V1, st + OFF_R1, s1, H_);

        sgemm_f32x2<1024, 8, true><<<gH, 256, smemH>>>(
            s1, w2, b2, nullptr,
            st + OFF_CUR2, st + OFF_V2, st + OFF_R2, s2, H_);

        sgemm_f32x2<1024, 4, false><<<gO, 256, smemO>>>(
            s2, w_out, nullptr, x3, nullptr, nullptr, nullptr, nullptr, OUT_);

        float* sp = st + ((t & 1) == 0 ? OFF_SO0 : OFF_SO1);
        float* sn = st + ((t & 1) == 0 ? OFF_SO1 : OFF_SO0);
        neuron_out_kernel<<<nboBlocks, 256>>>(x3, b_out, conn_w, conn_b, sp, sn,
            st + OFF_CURO, st + OFF_VO, st + OFF_RO, st + OFF_ACC);
    }

    decode_kernel<<<(B_ * AD_ + 255) / 256, 256>>>(st + OFF_ACC, dec_w, dec_b, out);
}